// round 1
// baseline (speedup 1.0000x reference)
#include <cuda_runtime.h>
#include <cstdint>
#include <cstddef>

#define BB 32
#define PP 24576
#define CC 80
#define OO 32
#define NTOPK 15
#define FULLM 0xffffffffu
#define NBLK (BB*PP/8)   // 98304 blocks for kA/kC

// ---------------- scratch (static device globals; no allocations) ----------------
__device__ float    g_q1v[BB*PP];
__device__ unsigned g_q1m[BB*PP];
__device__ float    g_qrv[BB*PP];
__device__ unsigned g_qrm[BB*PP];
__device__ float    g_thr[2*BB*OO];      // [type][b][o]
__device__ double   g_part[4*NBLK];      // per-block partials: 0 loc-num, 1 pos-cnt, 2 conf-num, 3 lab-cnt

// ---------------- helpers ----------------
__device__ __forceinline__ float warpMaxF(float v){
#pragma unroll
    for (int o = 16; o; o >>= 1) v = fmaxf(v, __shfl_xor_sync(FULLM, v, o));
    return v;
}
__device__ __forceinline__ float warpSumF(float v){
#pragma unroll
    for (int o = 16; o; o >>= 1) v += __shfl_xor_sync(FULLM, v, o);
    return v;
}
__device__ __forceinline__ float iou_box(float ax0,float ay0,float ax1,float ay1,float aa,
                                         float bx0,float by0,float bx1,float by1,float ba){
    float ix0 = fmaxf(ax0,bx0), iy0 = fmaxf(ay0,by0);
    float ix1 = fminf(ax1,bx1), iy1 = fminf(ay1,by1);
    float iw  = fmaxf(ix1-ix0, 0.f), ih = fmaxf(iy1-iy0, 0.f);
    float inter = iw*ih;
    return __fdividef(inter, aa + ba - inter + 1e-9f);
}

// ---------------- kernel A: per-(b,p) column stats for both assignment matrices ----------------
__global__ void __launch_bounds__(256) kA(const float* __restrict__ loc,
                                          const float* __restrict__ conf,
                                          const float* __restrict__ priors,
                                          const float* __restrict__ targets){
    __shared__ float st[OO*5];
    __shared__ float sarea[OO];
    __shared__ float so_q1v[8], so_qrv[8];
    __shared__ unsigned so_q1m[8], so_qrm[8];

    const int bpb = PP/8;
    const int b = blockIdx.x / bpb;
    const int p = (blockIdx.x % bpb)*8 + (threadIdx.x >> 5);
    const int lane = threadIdx.x & 31;
    const int tid = threadIdx.x;

    if (tid < OO*5) st[tid] = targets[b*OO*5 + tid];
    __syncthreads();
    if (tid < OO) sarea[tid] = (st[tid*5+2]-st[tid*5+0])*(st[tid*5+3]-st[tid*5+1]);
    __syncthreads();

    const float4 pr = reinterpret_cast<const float4*>(priors)[p];
    const float px0 = pr.x - pr.z*0.5f, py0 = pr.y - pr.w*0.5f;
    const float px1 = pr.x + pr.z*0.5f, py1 = pr.y + pr.w*0.5f;
    const float pa  = (px1-px0)*(py1-py0);

    const float4 lc = reinterpret_cast<const float4*>(loc)[(size_t)b*PP + p];
    float dw = 0.f, dh = 0.f;
    if (lane == 0){ dw = pr.z*__expf(lc.z*0.2f); dh = pr.w*__expf(lc.w*0.2f); }
    dw = __shfl_sync(FULLM, dw, 0);
    dh = __shfl_sync(FULLM, dh, 0);
    const float dcx = pr.x + lc.x*0.1f*pr.z;
    const float dcy = pr.y + lc.y*0.1f*pr.w;
    const float dx0 = dcx - dw*0.5f, dy0 = dcy - dh*0.5f;
    const float dx1 = dcx + dw*0.5f, dy1 = dcy + dh*0.5f;
    const float da  = (dx1-dx0)*(dy1-dy0);

    const int o = lane;
    const float tx0 = st[o*5+0], ty0 = st[o*5+1], tx1 = st[o*5+2], ty1 = st[o*5+3];
    const float ta  = sarea[o];
    const int  lab  = (int)st[o*5+4];

    const float ov = iou_box(tx0,ty0,tx1,ty1,ta, px0,py0,px1,py1,pa);
    const float q1 = iou_box(tx0,ty0,tx1,ty1,ta, dx0,dy0,dx1,dy1,da);

    const float q1max = warpMaxF(q1);
    const unsigned m1 = __ballot_sync(FULLM, q1 == q1max);

    const float cl = conf[((size_t)b*PP + p)*CC + lab];
    const float z  = __expf(-cl);
    const float pc = __fdividef(1.f, 1.f + z);
    const float lb = __log2f(fmaxf(ov, 1e-12f));
    const float qr = exp2f((1.0f - 0.5f*pc)*lb);

    const float qrmax = warpMaxF(qr);
    const unsigned mr = __ballot_sync(FULLM, qr == qrmax);

    const int w = threadIdx.x >> 5;
    if (lane == 0){ so_q1v[w]=q1max; so_q1m[w]=m1; so_qrv[w]=qrmax; so_qrm[w]=mr; }
    __syncthreads();
    if (tid < 8){
        const size_t base = (size_t)b*PP + (size_t)(blockIdx.x % bpb)*8 + tid;
        g_q1v[base] = so_q1v[tid]; g_q1m[base] = so_q1m[tid];
        g_qrv[base] = so_qrv[tid]; g_qrm[base] = so_qrm[tid];
    }
}

// ---------------- kernel B: per-(b,o,type) 15th-largest threshold ----------------
__global__ void __launch_bounds__(256) kB(){
    const int gw   = (blockIdx.x*blockDim.x + threadIdx.x) >> 5;  // 0..2047
    const int lane = threadIdx.x & 31;
    const int b    = gw >> 6;
    const int rem  = gw & 63;
    const int type = rem >> 5;
    const int o    = rem & 31;

    const float*    val = type ? g_qrv : g_q1v;
    const unsigned* msk = type ? g_qrm : g_q1m;
    const size_t base = (size_t)b*PP;

    float list[NTOPK];
#pragma unroll
    for (int i = 0; i < NTOPK; ++i) list[i] = 0.f;

    for (int p = lane; p < PP; p += 32){
        const float v = val[base+p];
        const unsigned m = msk[base+p];
        const float cand = ((m >> o) & 1u) ? v : 0.f;
        if (cand > list[NTOPK-1]){
            list[NTOPK-1] = cand;
#pragma unroll
            for (int j = NTOPK-1; j > 0; --j){
                if (list[j] > list[j-1]){ float t = list[j-1]; list[j-1] = list[j]; list[j] = t; }
            }
        }
    }

    // warp merge-pop: 15 rounds of argmax over sorted-list heads (all values >= 0)
    float thr = 0.f;
#pragma unroll 1
    for (int r = 0; r < NTOPK; ++r){
        unsigned long long key = ((unsigned long long)__float_as_uint(list[0]) << 32) | (unsigned)lane;
#pragma unroll
        for (int off = 16; off; off >>= 1){
            unsigned long long ok = __shfl_xor_sync(FULLM, key, off);
            if (ok > key) key = ok;
        }
        thr = __uint_as_float((unsigned)(key >> 32));
        const int wl = (int)(key & 31u);
        if (lane == wl){
#pragma unroll
            for (int j = 0; j < NTOPK-1; ++j) list[j] = list[j+1];
            list[NTOPK-1] = 0.f;   // sentinel: zeros are legitimate (and inexhaustible) candidates
        }
    }
    if (lane == 0) g_thr[type*BB*OO + b*OO + o] = thr;
}

// ---------------- kernel C: assignment finalize + fused losses ----------------
__global__ void __launch_bounds__(256) kC(const float* __restrict__ loc,
                                          const float* __restrict__ conf,
                                          const float* __restrict__ priors,
                                          const float* __restrict__ targets){
    __shared__ float st[OO*5];
    __shared__ float sthr1[OO], sthrr[OO];
    __shared__ double sacc[4];

    const int bpb = PP/8;
    const int b = blockIdx.x / bpb;
    const int p = (blockIdx.x % bpb)*8 + (threadIdx.x >> 5);
    const int lane = threadIdx.x & 31;
    const int tid = threadIdx.x;

    if (tid < OO*5) st[tid] = targets[b*OO*5 + tid];
    if (tid >= 192 && tid < 224) sthr1[tid-192] = g_thr[b*OO + (tid-192)];
    if (tid >= 224)              sthrr[tid-224] = g_thr[BB*OO + b*OO + (tid-224)];
    if (tid < 4) sacc[tid] = 0.0;
    __syncthreads();

    const size_t idx = (size_t)b*PP + p;
    const float v1 = g_q1v[idx]; const unsigned m1 = g_q1m[idx];
    const float vr = g_qrv[idx]; const unsigned mr = g_qrm[idx];

    const bool pass1 = ((m1 >> lane) & 1u) && (v1 > 0.f) && (v1 >= sthr1[lane]);
    const unsigned bal1 = __ballot_sync(FULLM, pass1);
    const bool passr = ((mr >> lane) & 1u) && (vr > 0.f) && (vr >= sthrr[lane]);
    const unsigned balr = __ballot_sync(FULLM, passr);

    const bool matched1 = (bal1 != 0);
    const bool pos      = (balr != 0);
    const int bo  = matched1 ? (__ffs(bal1)-1) : 0;
    const int bor = pos      ? (__ffs(balr)-1) : 0;
    const int tclass = matched1 ? (int)st[bo*5+4] : -1;

    // ---- gfocal over C=80 classes (mask == 1 everywhere; t nonzero at one class) ----
    const float* crow = conf + idx*CC;
    float acc_c = 0.f;
#pragma unroll
    for (int k = 0; k < 3; ++k){
        const int c = lane + k*32;
        if (c < CC){
            const float l = crow[c];
            const float t = (c == tclass) ? v1 : 0.f;
            const float za = __expf(-fabsf(l));
            const float r  = __fdividef(1.f, 1.f + za);
            const float ps = (l >= 0.f) ? r : (1.f - r);
            const float bce = fmaxf(l, 0.f) - l*t + __logf(1.f + za);
            const float d = t - ps;
            acc_c += d*d*bce;
        }
    }

    // ---- balanced L1 on positives ----
    float acc_l = 0.f;
    if (pos && lane < 4){
        const float4 pr = reinterpret_cast<const float4*>(priors)[p];
        const float mx0 = st[bor*5+0], my0 = st[bor*5+1], mx1 = st[bor*5+2], my1 = st[bor*5+3];
        float g;
        if      (lane == 0) g = ((mx0+mx1)*0.5f - pr.x) / (0.1f*pr.z);
        else if (lane == 1) g = ((my0+my1)*0.5f - pr.y) / (0.1f*pr.w);
        else if (lane == 2) g = logf(fmaxf((mx1-mx0)/pr.z, 1e-8f)) * 5.0f;
        else                g = logf(fmaxf((my1-my0)/pr.w, 1e-8f)) * 5.0f;
        const float pred = loc[idx*4 + lane];
        const float d = fabsf(pred - g);
        const float alpha = 0.5f, gamma = 1.5f, beta = 0.11f;
        const float eb = 19.085536923187668f; // e^(gamma/alpha) - 1
        const float small_ = alpha/eb*(eb*d + 1.0f)*log1pf(eb*d/beta) - alpha*d;
        const float big_   = gamma*d + gamma/eb - alpha*beta;
        acc_l = (d < beta) ? small_ : big_;
    }

    const float wc  = warpSumF(acc_c);
    const float wl_ = warpSumF(acc_l);
    if (lane == 0){
        atomicAdd(&sacc[0], (double)wl_);
        if (pos)      atomicAdd(&sacc[1], 1.0);
        atomicAdd(&sacc[2], (double)wc);
        if (matched1) atomicAdd(&sacc[3], 1.0);
    }
    __syncthreads();
    if (tid < 4) g_part[tid*NBLK + blockIdx.x] = sacc[tid];
}

// ---------------- final deterministic reduction ----------------
__global__ void __launch_bounds__(1024) kFinal(float* __restrict__ out){
    __shared__ double sh[4][32];
    double s[4] = {0.0, 0.0, 0.0, 0.0};
    for (int i = threadIdx.x; i < NBLK; i += 1024){
        s[0] += g_part[i];
        s[1] += g_part[NBLK + i];
        s[2] += g_part[2*NBLK + i];
        s[3] += g_part[3*NBLK + i];
    }
    const int lane = threadIdx.x & 31, w = threadIdx.x >> 5;
#pragma unroll
    for (int k = 0; k < 4; ++k){
        double v = s[k];
#pragma unroll
        for (int off = 16; off; off >>= 1) v += __shfl_xor_sync(FULLM, v, off);
        if (lane == 0) sh[k][w] = v;
    }
    __syncthreads();
    if (threadIdx.x < 32){
#pragma unroll
        for (int k = 0; k < 4; ++k){
            double v = sh[k][threadIdx.x];
#pragma unroll
            for (int off = 16; off; off >>= 1) v += __shfl_xor_sync(FULLM, v, off);
            if (threadIdx.x == 0) sh[k][0] = v;
        }
    }
    __syncthreads();
    if (threadIdx.x == 0){
        const double num_l = sh[0][0], cnt_p = sh[1][0], num_c = sh[2][0], cnt_l = sh[3][0];
        out[0] = (float)(num_l / fmax(cnt_p, 1.0));
        out[1] = (float)(num_c / fmax(cnt_l, 1.0));
    }
}

// ---------------- launch ----------------
extern "C" void kernel_launch(void* const* d_in, const int* in_sizes, int n_in,
                              void* d_out, int out_size){
    const float* loc     = (const float*)d_in[0];
    const float* conf    = (const float*)d_in[1];
    const float* priors  = (const float*)d_in[2];
    const float* targets = (const float*)d_in[3];
    float* out = (float*)d_out;

    kA<<<NBLK, 256>>>(loc, conf, priors, targets);
    kB<<<(2*BB*OO*32)/256, 256>>>();
    kC<<<NBLK, 256>>>(loc, conf, priors, targets);
    kFinal<<<1, 1024>>>(out);
}

// round 2
// speedup vs baseline: 2.6389x; 2.6389x over previous
#include <cuda_runtime.h>
#include <cstdint>
#include <cstddef>

#define BB 32
#define PP 24576
#define CC 80
#define OO 32
#define NTOPK 15
#define FULLM 0xffffffffu
#define NSEG 48                 // segments per batch item
#define NBLK (BB*NSEG)          // 1536 blocks for kA/kC

// ---------------- scratch (static device globals; no allocations) ----------------
__device__ float2   g_q1[BB*PP];        // (colmax value, bitcast tie-mask)
__device__ float2   g_qr[BB*PP];
__device__ float    g_thr[2*BB*OO];     // [type][b][o]
__device__ double   g_part[4*NBLK];     // 0 loc-num, 1 pos-cnt, 2 conf-num, 3 matched-cnt

// ---------------- helpers ----------------
__device__ __forceinline__ float warpMaxF(float v){
#pragma unroll
    for (int o = 16; o; o >>= 1) v = fmaxf(v, __shfl_xor_sync(FULLM, v, o));
    return v;
}
__device__ __forceinline__ float warpSumF(float v){
#pragma unroll
    for (int o = 16; o; o >>= 1) v += __shfl_xor_sync(FULLM, v, o);
    return v;
}
__device__ __forceinline__ float iou_box(float ax0,float ay0,float ax1,float ay1,float aa,
                                         float bx0,float by0,float bx1,float by1,float ba){
    float ix0 = fmaxf(ax0,bx0), iy0 = fmaxf(ay0,by0);
    float ix1 = fminf(ax1,bx1), iy1 = fminf(ay1,by1);
    float iw  = fmaxf(ix1-ix0, 0.f), ih = fmaxf(iy1-iy0, 0.f);
    float inter = iw*ih;
    return __fdividef(inter, aa + ba - inter + 1e-9f);
}

// ---------------- kernel A: per-(b,p) column stats for both assignment matrices ----------------
__global__ void __launch_bounds__(256) kA(const float* __restrict__ loc,
                                          const float* __restrict__ conf,
                                          const float* __restrict__ priors,
                                          const float* __restrict__ targets){
    __shared__ float st[OO*5];
    __shared__ float sarea[OO];

    const int b   = blockIdx.x / NSEG;
    const int seg = blockIdx.x % NSEG;
    const int w    = threadIdx.x >> 5;
    const int lane = threadIdx.x & 31;
    const int tid  = threadIdx.x;

    if (tid < OO*5) st[tid] = targets[b*OO*5 + tid];
    __syncthreads();
    if (tid < OO) sarea[tid] = (st[tid*5+2]-st[tid*5+0])*(st[tid*5+3]-st[tid*5+1]);
    __syncthreads();

    const int o = lane;
    const float tx0 = st[o*5+0], ty0 = st[o*5+1], tx1 = st[o*5+2], ty1 = st[o*5+3];
    const float ta  = sarea[o];
    const int  lab  = (int)st[o*5+4];

    const int pbase = seg*512 + w*64;
    const size_t bbase = (size_t)b*PP;

    float2 keep1 = make_float2(0.f,0.f), keepr = make_float2(0.f,0.f);

#pragma unroll 2
    for (int j = 0; j < 64; ++j){
        const int p = pbase + j;
        const float4 pr = __ldg(&reinterpret_cast<const float4*>(priors)[p]);
        const float px0 = pr.x - pr.z*0.5f, py0 = pr.y - pr.w*0.5f;
        const float px1 = pr.x + pr.z*0.5f, py1 = pr.y + pr.w*0.5f;
        const float pa  = pr.z * pr.w;

        const size_t idx = bbase + p;
        const float4 lc = __ldg(&reinterpret_cast<const float4*>(loc)[idx]);
        const float dw = pr.z * __expf(lc.z*0.2f);
        const float dh = pr.w * __expf(lc.w*0.2f);
        const float dcx = pr.x + lc.x*0.1f*pr.z;
        const float dcy = pr.y + lc.y*0.1f*pr.w;
        const float dx0 = dcx - dw*0.5f, dy0 = dcy - dh*0.5f;
        const float dx1 = dcx + dw*0.5f, dy1 = dcy + dh*0.5f;
        const float da  = dw*dh;

        const float ov = iou_box(tx0,ty0,tx1,ty1,ta, px0,py0,px1,py1,pa);
        const float q1 = iou_box(tx0,ty0,tx1,ty1,ta, dx0,dy0,dx1,dy1,da);

        const float q1max = warpMaxF(q1);
        const unsigned m1 = __ballot_sync(FULLM, q1 == q1max);

        const float cl = __ldg(&conf[idx*CC + lab]);
        const float pc = __fdividef(1.f, 1.f + __expf(-cl));
        const float lb = __log2f(fmaxf(ov, 1e-12f));
        const float qr = exp2f((1.0f - 0.5f*pc)*lb);

        const float qrmax = warpMaxF(qr);
        const unsigned mr = __ballot_sync(FULLM, qr == qrmax);

        if (lane == (j & 31)){
            keep1 = make_float2(q1max, __uint_as_float(m1));
            keepr = make_float2(qrmax, __uint_as_float(mr));
        }
        if ((j & 31) == 31){
            const size_t sidx = bbase + pbase + (j - 31) + lane;
            g_q1[sidx] = keep1;
            g_qr[sidx] = keepr;
        }
    }
}

// ---------------- kernel B: per-(b,o,type) 15th-largest threshold ----------------
__global__ void __launch_bounds__(256) kB(){
    const int gw   = (blockIdx.x*blockDim.x + threadIdx.x) >> 5;  // 0..2047
    const int lane = threadIdx.x & 31;
    const int b    = gw >> 6;
    const int rem  = gw & 63;
    const int type = rem >> 5;
    const int o    = rem & 31;

    const float2* __restrict__ dat = type ? g_qr : g_q1;
    const size_t base = (size_t)b*PP;

    float list[NTOPK];
#pragma unroll
    for (int i = 0; i < NTOPK; ++i) list[i] = 0.f;

    // PP = 24576 = 32 * 768; 96 outer iterations of 8-wide unroll -> MLP 8
    for (int i0 = lane; i0 < PP; i0 += 32*8){
        float2 v[8];
#pragma unroll
        for (int j = 0; j < 8; ++j) v[j] = __ldg(&dat[base + i0 + 32*j]);
#pragma unroll
        for (int j = 0; j < 8; ++j){
            const unsigned m = __float_as_uint(v[j].y);
            const float cand = ((m >> o) & 1u) ? v[j].x : 0.f;
            if (cand > list[NTOPK-1]){
                list[NTOPK-1] = cand;
#pragma unroll
                for (int k = NTOPK-1; k > 0; --k){
                    if (list[k] > list[k-1]){ float t = list[k-1]; list[k-1] = list[k]; list[k] = t; }
                }
            }
        }
    }

    // warp merge-pop: 15 rounds of argmax over sorted-list heads (all values >= 0)
    float thr = 0.f;
#pragma unroll 1
    for (int r = 0; r < NTOPK; ++r){
        unsigned long long key = ((unsigned long long)__float_as_uint(list[0]) << 32) | (unsigned)lane;
#pragma unroll
        for (int off = 16; off; off >>= 1){
            unsigned long long ok = __shfl_xor_sync(FULLM, key, off);
            if (ok > key) key = ok;
        }
        thr = __uint_as_float((unsigned)(key >> 32));
        const int wl = (int)(key & 31u);
        if (lane == wl){
#pragma unroll
            for (int j = 0; j < NTOPK-1; ++j) list[j] = list[j+1];
            list[NTOPK-1] = 0.f;
        }
    }
    if (lane == 0) g_thr[type*BB*OO + b*OO + o] = thr;
}

// ---------------- kernel C: assignment finalize + fused losses ----------------
__global__ void __launch_bounds__(256) kC(const float* __restrict__ loc,
                                          const float* __restrict__ conf,
                                          const float* __restrict__ priors,
                                          const float* __restrict__ targets){
    __shared__ float st[OO*5];
    __shared__ float sthr1[OO], sthrr[OO];
    __shared__ double sacc[4];

    const int b   = blockIdx.x / NSEG;
    const int seg = blockIdx.x % NSEG;
    const int w    = threadIdx.x >> 5;
    const int lane = threadIdx.x & 31;
    const int tid  = threadIdx.x;

    if (tid < OO*5) st[tid] = targets[b*OO*5 + tid];
    if (tid >= 192 && tid < 224) sthr1[tid-192] = g_thr[b*OO + (tid-192)];
    if (tid >= 224)              sthrr[tid-224] = g_thr[BB*OO + b*OO + (tid-224)];
    if (tid < 4) sacc[tid] = 0.0;
    __syncthreads();

    const int pbase = seg*512 + w*64;
    const size_t bbase = (size_t)b*PP;
    const float thr1 = sthr1[lane];
    const float thrr = sthrr[lane];

    float accC = 0.f, accL = 0.f;
    int cntP = 0, cntM = 0;

#pragma unroll 2
    for (int j = 0; j < 64; ++j){
        const int p = pbase + j;
        const size_t idx = bbase + p;

        const float2 a = g_q1[idx];
        const float2 r = g_qr[idx];
        const float v1 = a.x; const unsigned m1 = __float_as_uint(a.y);
        const float vr = r.x; const unsigned mr = __float_as_uint(r.y);

        const bool pass1 = ((m1 >> lane) & 1u) && (v1 > 0.f) && (v1 >= thr1);
        const unsigned bal1 = __ballot_sync(FULLM, pass1);
        const bool passr = ((mr >> lane) & 1u) && (vr > 0.f) && (vr >= thrr);
        const unsigned balr = __ballot_sync(FULLM, passr);

        const bool matched1 = (bal1 != 0);
        const bool pos      = (balr != 0);
        const int bo  = matched1 ? (__ffs(bal1)-1) : 0;
        const int bor = pos      ? (__ffs(balr)-1) : 0;
        const int tclass = matched1 ? (int)st[bo*5+4] : -1;

        // ---- gfocal over C=80 classes ----
        const float* crow = conf + idx*CC;
#pragma unroll
        for (int k = 0; k < 3; ++k){
            const int c = lane + k*32;
            if (c < CC){
                const float l = __ldg(&crow[c]);
                const float t = (c == tclass) ? v1 : 0.f;
                const float za = __expf(-fabsf(l));
                const float rr = __fdividef(1.f, 1.f + za);
                const float ps = (l >= 0.f) ? rr : (1.f - rr);
                const float bce = fmaxf(l, 0.f) - l*t + __logf(1.f + za);
                const float d = t - ps;
                accC += d*d*bce;
            }
        }

        // ---- balanced L1 on positives ----
        if (pos){
            if (lane < 4){
                const float4 pr = __ldg(&reinterpret_cast<const float4*>(priors)[p]);
                const float mx0 = st[bor*5+0], my0 = st[bor*5+1];
                const float mx1 = st[bor*5+2], my1 = st[bor*5+3];
                float g;
                if      (lane == 0) g = ((mx0+mx1)*0.5f - pr.x) / (0.1f*pr.z);
                else if (lane == 1) g = ((my0+my1)*0.5f - pr.y) / (0.1f*pr.w);
                else if (lane == 2) g = logf(fmaxf((mx1-mx0)/pr.z, 1e-8f)) * 5.0f;
                else                g = logf(fmaxf((my1-my0)/pr.w, 1e-8f)) * 5.0f;
                const float pred = __ldg(&loc[idx*4 + lane]);
                const float d = fabsf(pred - g);
                const float alpha = 0.5f, gamma = 1.5f, beta = 0.11f;
                const float eb = 19.085536923187668f; // e^(gamma/alpha) - 1
                const float small_ = alpha/eb*(eb*d + 1.0f)*log1pf(eb*d/beta) - alpha*d;
                const float big_   = gamma*d + gamma/eb - alpha*beta;
                accL += (d < beta) ? small_ : big_;
            }
            ++cntP;
        }
        if (matched1) ++cntM;
    }

    const float wc  = warpSumF(accC);
    const float wl_ = warpSumF(accL);
    if (lane == 0){
        atomicAdd(&sacc[0], (double)wl_);
        atomicAdd(&sacc[1], (double)cntP);
        atomicAdd(&sacc[2], (double)wc);
        atomicAdd(&sacc[3], (double)cntM);
    }
    __syncthreads();
    if (tid < 4) g_part[tid*NBLK + blockIdx.x] = sacc[tid];
}

// ---------------- final deterministic reduction (1536 partials/metric) ----------------
__global__ void __launch_bounds__(512) kFinal(float* __restrict__ out){
    __shared__ double sh[4][16];
    double s[4] = {0.0, 0.0, 0.0, 0.0};
    for (int i = threadIdx.x; i < NBLK; i += 512){
#pragma unroll
        for (int k = 0; k < 4; ++k) s[k] += g_part[k*NBLK + i];
    }
    const int lane = threadIdx.x & 31, w = threadIdx.x >> 5;
#pragma unroll
    for (int k = 0; k < 4; ++k){
        double v = s[k];
#pragma unroll
        for (int off = 16; off; off >>= 1) v += __shfl_xor_sync(FULLM, v, off);
        if (lane == 0) sh[k][w] = v;
    }
    __syncthreads();
    if (threadIdx.x == 0){
        double num_l = 0, cnt_p = 0, num_c = 0, cnt_l = 0;
#pragma unroll
        for (int i = 0; i < 16; ++i){
            num_l += sh[0][i]; cnt_p += sh[1][i];
            num_c += sh[2][i]; cnt_l += sh[3][i];
        }
        out[0] = (float)(num_l / fmax(cnt_p, 1.0));
        out[1] = (float)(num_c / fmax(cnt_l, 1.0));
    }
}

// ---------------- launch ----------------
extern "C" void kernel_launch(void* const* d_in, const int* in_sizes, int n_in,
                              void* d_out, int out_size){
    const float* loc     = (const float*)d_in[0];
    const float* conf    = (const float*)d_in[1];
    const float* priors  = (const float*)d_in[2];
    const float* targets = (const float*)d_in[3];
    float* out = (float*)d_out;

    kA<<<NBLK, 256>>>(loc, conf, priors, targets);
    kB<<<(2*BB*OO*32)/256, 256>>>();
    kC<<<NBLK, 256>>>(loc, conf, priors, targets);
    kFinal<<<1, 512>>>(out);
}

// round 3
// speedup vs baseline: 3.4049x; 1.2903x over previous
#include <cuda_runtime.h>
#include <cstdint>
#include <cstddef>

#define BB 32
#define PP 24576
#define CC 80
#define OO 32
#define NTOPK 15
#define FULLM 0xffffffffu
#define NSEG 48                 // segments per batch item (kA)
#define NBLK (BB*NSEG)          // 1536 blocks for kA
#define NCB  (BB*PP/256)        // 3072 blocks for kC'

// ---------------- scratch ----------------
__device__ float2   g_q1[BB*PP];        // (colmax value, bitcast tie-mask)
__device__ float2   g_qr[BB*PP];
__device__ float    g_thr[2*BB*OO];     // [type][b][o]
__device__ double   g_basC[NBLK];       // conf base (t=0 gfocal) partials from kA
__device__ double   g_pc[4*NCB];        // kC': 0 loc-num, 1 pos-cnt, 2 conf-corr, 3 matched-cnt

// ---------------- helpers ----------------
__device__ __forceinline__ float warpMaxF(float v){
#pragma unroll
    for (int o = 16; o; o >>= 1) v = fmaxf(v, __shfl_xor_sync(FULLM, v, o));
    return v;
}
__device__ __forceinline__ float warpSumF(float v){
#pragma unroll
    for (int o = 16; o; o >>= 1) v += __shfl_xor_sync(FULLM, v, o);
    return v;
}
__device__ __forceinline__ float iou_box(float ax0,float ay0,float ax1,float ay1,float aa,
                                         float bx0,float by0,float bx1,float by1,float ba){
    float ix0 = fmaxf(ax0,bx0), iy0 = fmaxf(ay0,by0);
    float ix1 = fminf(ax1,bx1), iy1 = fminf(ay1,by1);
    float iw  = fmaxf(ix1-ix0, 0.f), ih = fmaxf(iy1-iy0, 0.f);
    float inter = iw*ih;
    return __fdividef(inter, aa + ba - inter + 1e-9f);
}
__device__ __forceinline__ float balanced_l1(float d){
    const float alpha = 0.5f, gamma = 1.5f, beta = 0.11f;
    const float eb = 19.085536923187668f; // e^(gamma/alpha) - 1
    const float small_ = alpha/eb*(eb*d + 1.0f)*log1pf(eb*d/beta) - alpha*d;
    const float big_   = gamma*d + gamma/eb - alpha*beta;
    return (d < beta) ? small_ : big_;
}

// ---------------- kernel A: column stats + gfocal base sum ----------------
__global__ void __launch_bounds__(256) kA(const float* __restrict__ loc,
                                          const float* __restrict__ conf,
                                          const float* __restrict__ priors,
                                          const float* __restrict__ targets){
    __shared__ float st[OO*5];
    __shared__ float sarea[OO];
    __shared__ float4 s_pf[8*64];
    __shared__ float4 s_dec[8*64];
    __shared__ float2 s_ar[8*64];
    __shared__ float s_cacc[8];

    const int b   = blockIdx.x / NSEG;
    const int seg = blockIdx.x % NSEG;
    const int w    = threadIdx.x >> 5;
    const int lane = threadIdx.x & 31;
    const int tid  = threadIdx.x;

    if (tid < OO*5) st[tid] = targets[b*OO*5 + tid];
    __syncthreads();
    if (tid < OO) sarea[tid] = (st[tid*5+2]-st[tid*5+0])*(st[tid*5+3]-st[tid*5+1]);
    __syncthreads();

    const int pbase = seg*512 + w*64;
    const size_t bbase = (size_t)b*PP;

    // ---- phase 1: each lane decodes 2 priors into smem ----
#pragma unroll
    for (int jj = lane; jj < 64; jj += 32){
        const int p = pbase + jj;
        const float4 pr = __ldg(&reinterpret_cast<const float4*>(priors)[p]);
        const float4 lc = __ldg(&reinterpret_cast<const float4*>(loc)[bbase + p]);
        const float px0 = pr.x - pr.z*0.5f, py0 = pr.y - pr.w*0.5f;
        const float px1 = pr.x + pr.z*0.5f, py1 = pr.y + pr.w*0.5f;
        const float dw = pr.z * __expf(lc.z*0.2f);
        const float dh = pr.w * __expf(lc.w*0.2f);
        const float dcx = pr.x + lc.x*0.1f*pr.z;
        const float dcy = pr.y + lc.y*0.1f*pr.w;
        s_pf [w*64+jj] = make_float4(px0, py0, px1, py1);
        s_dec[w*64+jj] = make_float4(dcx - dw*0.5f, dcy - dh*0.5f, dcx + dw*0.5f, dcy + dh*0.5f);
        s_ar [w*64+jj] = make_float2(pr.z*pr.w, dw*dh);
    }
    __syncwarp();

    const int o = lane;
    const float tx0 = st[o*5+0], ty0 = st[o*5+1], tx1 = st[o*5+2], ty1 = st[o*5+3];
    const float ta  = sarea[o];
    const int  lab  = (int)st[o*5+4];

    float2 keep1 = make_float2(0.f,0.f), keepr = make_float2(0.f,0.f);
    float accC = 0.f;

#pragma unroll 2
    for (int j = 0; j < 64; ++j){
        const float4 pf = s_pf [w*64+j];
        const float4 dc = s_dec[w*64+j];
        const float2 ar = s_ar [w*64+j];
        const size_t idx = bbase + pbase + j;

        const float ov = iou_box(tx0,ty0,tx1,ty1,ta, pf.x,pf.y,pf.z,pf.w, ar.x);
        const float q1 = iou_box(tx0,ty0,tx1,ty1,ta, dc.x,dc.y,dc.z,dc.w, ar.y);

        const float q1max = warpMaxF(q1);
        const unsigned m1 = __ballot_sync(FULLM, q1 == q1max);

        const float* crow = conf + idx*CC;
        const float cl = __ldg(&crow[lab]);
        const float pc = __fdividef(1.f, 1.f + __expf(-cl));
        const float lb = __log2f(fmaxf(ov, 1e-12f));
        const float qr = exp2f((1.0f - 0.5f*pc)*lb);

        const float qrmax = warpMaxF(qr);
        const unsigned mr = __ballot_sync(FULLM, qr == qrmax);

        if (lane == (j & 31)){
            keep1 = make_float2(q1max, __uint_as_float(m1));
            keepr = make_float2(qrmax, __uint_as_float(mr));
        }
        if ((j & 31) == 31){
            const size_t sidx = bbase + pbase + (j - 31) + lane;
            g_q1[sidx] = keep1;
            g_qr[sidx] = keepr;
        }

        // ---- gfocal base: t=0 term = sigmoid(l)^2 * softplus(l), all classes ----
#pragma unroll
        for (int k = 0; k < 3; ++k){
            const int c = lane + k*32;
            if (c < CC){
                const float l = __ldg(&crow[c]);
                const float e = __expf(-fabsf(l));
                const float r = __fdividef(1.f, 1.f + e);
                const float ps = (l >= 0.f) ? r : (1.f - r);
                const float sp = fmaxf(l, 0.f) + __logf(1.f + e);
                accC += ps*ps*sp;
            }
        }
    }

    const float wc = warpSumF(accC);
    if (lane == 0) s_cacc[w] = wc;
    __syncthreads();
    if (tid == 0){
        double s = 0.0;
#pragma unroll
        for (int i = 0; i < 8; ++i) s += (double)s_cacc[i];
        g_basC[blockIdx.x] = s;
    }
}

// ---------------- kernel B: per-(b,o,type) 15th-largest threshold ----------------
__global__ void __launch_bounds__(256) kB(){
    const int gw   = (blockIdx.x*blockDim.x + threadIdx.x) >> 5;  // 0..2047
    const int lane = threadIdx.x & 31;
    const int b    = gw >> 6;
    const int rem  = gw & 63;
    const int type = rem >> 5;
    const int o    = rem & 31;

    const float2* __restrict__ dat = type ? g_qr : g_q1;
    const size_t base = (size_t)b*PP;

    float list[NTOPK];
#pragma unroll
    for (int i = 0; i < NTOPK; ++i) list[i] = 0.f;

    for (int i0 = lane; i0 < PP; i0 += 32*8){
        float2 v[8];
#pragma unroll
        for (int j = 0; j < 8; ++j) v[j] = __ldg(&dat[base + i0 + 32*j]);
#pragma unroll
        for (int j = 0; j < 8; ++j){
            const unsigned m = __float_as_uint(v[j].y);
            const float cand = ((m >> o) & 1u) ? v[j].x : 0.f;
            if (cand > list[NTOPK-1]){
                list[NTOPK-1] = cand;
#pragma unroll
                for (int k = NTOPK-1; k > 0; --k){
                    if (list[k] > list[k-1]){ float t = list[k-1]; list[k-1] = list[k]; list[k] = t; }
                }
            }
        }
    }

    float thr = 0.f;
#pragma unroll 1
    for (int r = 0; r < NTOPK; ++r){
        unsigned long long key = ((unsigned long long)__float_as_uint(list[0]) << 32) | (unsigned)lane;
#pragma unroll
        for (int off = 16; off; off >>= 1){
            unsigned long long ok = __shfl_xor_sync(FULLM, key, off);
            if (ok > key) key = ok;
        }
        thr = __uint_as_float((unsigned)(key >> 32));
        const int wl = (int)(key & 31u);
        if (lane == wl){
#pragma unroll
            for (int j = 0; j < NTOPK-1; ++j) list[j] = list[j+1];
            list[NTOPK-1] = 0.f;
        }
    }
    if (lane == 0) g_thr[type*BB*OO + b*OO + o] = thr;
}

// ---------------- kernel C': sparse corrections (thread per prior) ----------------
__global__ void __launch_bounds__(256) kC(const float* __restrict__ loc,
                                          const float* __restrict__ conf,
                                          const float* __restrict__ priors,
                                          const float* __restrict__ targets){
    __shared__ float st[OO*5];
    __shared__ float sthr1[OO], sthrr[OO];
    __shared__ float s_l[8], s_c[8];
    __shared__ int   s_p[8], s_m[8];

    const int blocks_per_b = NCB / BB;        // 96
    const int b   = blockIdx.x / blocks_per_b;
    const int seg = blockIdx.x % blocks_per_b;
    const int tid = threadIdx.x;
    const int lane = tid & 31;
    const int w = tid >> 5;

    if (tid < OO*5) st[tid] = targets[b*OO*5 + tid];
    if (tid >= 192 && tid < 224) sthr1[tid-192] = g_thr[b*OO + (tid-192)];
    if (tid >= 224)              sthrr[tid-224] = g_thr[BB*OO + b*OO + (tid-224)];
    __syncthreads();

    const int p = seg*256 + tid;
    const size_t idx = (size_t)b*PP + p;

    const float2 a = g_q1[idx];
    const float2 r = g_qr[idx];
    const float v1 = a.x; unsigned m1 = __float_as_uint(a.y);
    const float vr = r.x; unsigned mr = __float_as_uint(r.y);

    int bo = -1;
    if (v1 > 0.f){
#pragma unroll 1
        while (m1){
            const int oo = __ffs(m1) - 1;
            if (v1 >= sthr1[oo]){ bo = oo; break; }
            m1 &= m1 - 1;
        }
    }
    int bor = -1;
    if (vr > 0.f){
#pragma unroll 1
        while (mr){
            const int oo = __ffs(mr) - 1;
            if (vr >= sthrr[oo]){ bor = oo; break; }
            mr &= mr - 1;
        }
    }

    float accC = 0.f, accL = 0.f;
    int cntM = 0, cntP = 0;

    if (bo >= 0){
        cntM = 1;
        const int tclass = (int)st[bo*5+4];
        const float l = __ldg(&conf[idx*CC + tclass]);
        const float t = v1;
        const float e = __expf(-fabsf(l));
        const float rr = __fdividef(1.f, 1.f + e);
        const float ps = (l >= 0.f) ? rr : (1.f - rr);
        const float sp = fmaxf(l, 0.f) + __logf(1.f + e);
        const float d = t - ps;
        accC = d*d*(sp - l*t) - ps*ps*sp;   // f(l,t) - f0(l)
    }
    if (bor >= 0){
        cntP = 1;
        const float4 pr = __ldg(&reinterpret_cast<const float4*>(priors)[p]);
        const float4 lc = __ldg(&reinterpret_cast<const float4*>(loc)[idx]);
        const float mx0 = st[bor*5+0], my0 = st[bor*5+1];
        const float mx1 = st[bor*5+2], my1 = st[bor*5+3];
        const float gx = ((mx0+mx1)*0.5f - pr.x) / (0.1f*pr.z);
        const float gy = ((my0+my1)*0.5f - pr.y) / (0.1f*pr.w);
        const float gw = logf(fmaxf((mx1-mx0)/pr.z, 1e-8f)) * 5.0f;
        const float gh = logf(fmaxf((my1-my0)/pr.w, 1e-8f)) * 5.0f;
        accL  = balanced_l1(fabsf(lc.x - gx));
        accL += balanced_l1(fabsf(lc.y - gy));
        accL += balanced_l1(fabsf(lc.z - gw));
        accL += balanced_l1(fabsf(lc.w - gh));
    }

    const float wl_ = warpSumF(accL);
    const float wc  = warpSumF(accC);
    int ip = cntP, im = cntM;
#pragma unroll
    for (int off = 16; off; off >>= 1){
        ip += __shfl_xor_sync(FULLM, ip, off);
        im += __shfl_xor_sync(FULLM, im, off);
    }
    if (lane == 0){ s_l[w] = wl_; s_c[w] = wc; s_p[w] = ip; s_m[w] = im; }
    __syncthreads();
    if (tid == 0){
        double dl = 0, dc = 0; int pp2 = 0, mm = 0;
#pragma unroll
        for (int i = 0; i < 8; ++i){ dl += (double)s_l[i]; dc += (double)s_c[i]; pp2 += s_p[i]; mm += s_m[i]; }
        g_pc[0*NCB + blockIdx.x] = dl;
        g_pc[1*NCB + blockIdx.x] = (double)pp2;
        g_pc[2*NCB + blockIdx.x] = dc;
        g_pc[3*NCB + blockIdx.x] = (double)mm;
    }
}

// ---------------- final reduction ----------------
__global__ void __launch_bounds__(1024) kFinal(float* __restrict__ out){
    __shared__ double sh[5][32];
    double s[5] = {0,0,0,0,0};
    for (int i = threadIdx.x; i < NCB; i += 1024){
#pragma unroll
        for (int k = 0; k < 4; ++k) s[k] += g_pc[k*NCB + i];
    }
    for (int i = threadIdx.x; i < NBLK; i += 1024) s[4] += g_basC[i];

    const int lane = threadIdx.x & 31, w = threadIdx.x >> 5;
#pragma unroll
    for (int k = 0; k < 5; ++k){
        double v = s[k];
#pragma unroll
        for (int off = 16; off; off >>= 1) v += __shfl_xor_sync(FULLM, v, off);
        if (lane == 0) sh[k][w] = v;
    }
    __syncthreads();
    if (threadIdx.x == 0){
        double t[5] = {0,0,0,0,0};
#pragma unroll
        for (int i = 0; i < 32; ++i){
#pragma unroll
            for (int k = 0; k < 5; ++k) t[k] += sh[k][i];
        }
        const double num_l = t[0], cnt_p = t[1], num_c = t[2] + t[4], cnt_m = t[3];
        out[0] = (float)(num_l / fmax(cnt_p, 1.0));
        out[1] = (float)(num_c / fmax(cnt_m, 1.0));
    }
}

// ---------------- launch ----------------
extern "C" void kernel_launch(void* const* d_in, const int* in_sizes, int n_in,
                              void* d_out, int out_size){
    const float* loc     = (const float*)d_in[0];
    const float* conf    = (const float*)d_in[1];
    const float* priors  = (const float*)d_in[2];
    const float* targets = (const float*)d_in[3];
    float* out = (float*)d_out;

    kA<<<NBLK, 256>>>(loc, conf, priors, targets);
    kB<<<(2*BB*OO*32)/256, 256>>>();
    kC<<<NCB, 256>>>(loc, conf, priors, targets);
    kFinal<<<1, 1024>>>(out);
}

// round 4
// speedup vs baseline: 3.4252x; 1.0060x over previous
#include <cuda_runtime.h>
#include <cstdint>
#include <cstddef>
#include <math_constants.h>

#define BB 32
#define PP 24576
#define CC 80
#define OO 32
#define NTOPK 15
#define FULLM 0xffffffffu
#define NSEG 48                 // segments per batch item (kA)
#define NBLK (BB*NSEG)          // 1536 blocks for kA
#define NCB2 (BB*PP/1024)       // 768 blocks for kC

// ---------------- scratch ----------------
__device__ float2   g_q1[BB*PP];        // (colmax q1, tie-mask)   q1 linear (can be 0)
__device__ float2   g_qr[BB*PP];        // (colmax lqr, tie-mask)  lqr = log2-domain (<= 0)
__device__ float    g_thr[2*BB*OO];     // [type][b][o]
__device__ double   g_basC[NBLK];       // conf base (t=0 gfocal) partials from kA
__device__ double   g_pc[NCB2*4];       // kC partials: [block][0 loc,1 pos,2 confcorr,3 matched]

// ---------------- helpers ----------------
__device__ __forceinline__ float warpMaxF(float v){
#pragma unroll
    for (int o = 16; o; o >>= 1) v = fmaxf(v, __shfl_xor_sync(FULLM, v, o));
    return v;
}
__device__ __forceinline__ float warpSumF(float v){
#pragma unroll
    for (int o = 16; o; o >>= 1) v += __shfl_xor_sync(FULLM, v, o);
    return v;
}
__device__ __forceinline__ float iou_box(float ax0,float ay0,float ax1,float ay1,float aa,
                                         float bx0,float by0,float bx1,float by1,float ba){
    float ix0 = fmaxf(ax0,bx0), iy0 = fmaxf(ay0,by0);
    float ix1 = fminf(ax1,bx1), iy1 = fminf(ay1,by1);
    float iw  = fmaxf(ix1-ix0, 0.f), ih = fmaxf(iy1-iy0, 0.f);
    float inter = iw*ih;
    return __fdividef(inter, aa + ba - inter + 1e-9f);
}
__device__ __forceinline__ float balanced_l1(float d){
    const float alpha = 0.5f, gamma = 1.5f, beta = 0.11f;
    const float eb = 19.085536923187668f; // e^(gamma/alpha) - 1
    const float small_ = alpha/eb*(eb*d + 1.0f)*log1pf(eb*d/beta) - alpha*d;
    const float big_   = gamma*d + gamma/eb - alpha*beta;
    return (d < beta) ? small_ : big_;
}

// ---------------- kernel A: column stats + gfocal base sum ----------------
__global__ void __launch_bounds__(256) kA(const float* __restrict__ loc,
                                          const float* __restrict__ conf,
                                          const float* __restrict__ priors,
                                          const float* __restrict__ targets){
    __shared__ float st[OO*5];
    __shared__ float sarea[OO];
    __shared__ float4 s_pf[8*64];
    __shared__ float4 s_dec[8*64];
    __shared__ float2 s_ar[8*64];
    __shared__ float s_cacc[8];

    const int b   = blockIdx.x / NSEG;
    const int seg = blockIdx.x % NSEG;
    const int w    = threadIdx.x >> 5;
    const int lane = threadIdx.x & 31;
    const int tid  = threadIdx.x;

    if (tid < OO*5) st[tid] = targets[b*OO*5 + tid];
    __syncthreads();
    if (tid < OO) sarea[tid] = (st[tid*5+2]-st[tid*5+0])*(st[tid*5+3]-st[tid*5+1]);
    __syncthreads();

    const int pbase = seg*512 + w*64;
    const size_t bbase = (size_t)b*PP;

    // ---- phase 1: each lane decodes 2 priors into smem ----
#pragma unroll
    for (int jj = lane; jj < 64; jj += 32){
        const int p = pbase + jj;
        const float4 pr = __ldg(&reinterpret_cast<const float4*>(priors)[p]);
        const float4 lc = __ldg(&reinterpret_cast<const float4*>(loc)[bbase + p]);
        const float px0 = pr.x - pr.z*0.5f, py0 = pr.y - pr.w*0.5f;
        const float px1 = pr.x + pr.z*0.5f, py1 = pr.y + pr.w*0.5f;
        const float dw = pr.z * __expf(lc.z*0.2f);
        const float dh = pr.w * __expf(lc.w*0.2f);
        const float dcx = pr.x + lc.x*0.1f*pr.z;
        const float dcy = pr.y + lc.y*0.1f*pr.w;
        s_pf [w*64+jj] = make_float4(px0, py0, px1, py1);
        s_dec[w*64+jj] = make_float4(dcx - dw*0.5f, dcy - dh*0.5f, dcx + dw*0.5f, dcy + dh*0.5f);
        s_ar [w*64+jj] = make_float2(pr.z*pr.w, dw*dh);
    }
    __syncwarp();

    const int o = lane;
    const float tx0 = st[o*5+0], ty0 = st[o*5+1], tx1 = st[o*5+2], ty1 = st[o*5+3];
    const float ta  = sarea[o];
    const int  lab  = (int)st[o*5+4];

    float2 keep1 = make_float2(0.f,0.f), keepr = make_float2(0.f,0.f);
    float accC = 0.f;

#pragma unroll 2
    for (int j = 0; j < 64; ++j){
        const float4 pf = s_pf [w*64+j];
        const float4 dc = s_dec[w*64+j];
        const float2 ar = s_ar [w*64+j];
        const size_t idx = bbase + pbase + j;
        const float* crow = conf + idx*CC;

        // ---- gfocal base first: warms L1 with the full row ----
#pragma unroll
        for (int k = 0; k < 3; ++k){
            const int c = lane + k*32;
            if (c < CC){
                const float l = __ldg(&crow[c]);
                const float e = __expf(-fabsf(l));
                const float r = __fdividef(1.f, 1.f + e);
                const float ps = (l >= 0.f) ? r : (1.f - r);
                const float sp = fmaxf(l, 0.f) + __logf(1.f + e);
                accC += ps*ps*sp;
            }
        }

        const float ov = iou_box(tx0,ty0,tx1,ty1,ta, pf.x,pf.y,pf.z,pf.w, ar.x);
        const float q1 = iou_box(tx0,ty0,tx1,ty1,ta, dc.x,dc.y,dc.z,dc.w, ar.y);

        const float q1max = warpMaxF(q1);
        const unsigned m1 = __ballot_sync(FULLM, q1 == q1max);

        // log-domain qr: lqr = (1 - pc/2) * log2(max(ov,1e-12)); order/tie preserving
        const float cl = __ldg(&crow[lab]);
        const float pc = __fdividef(1.f, 1.f + __expf(-cl));
        const float lb = __log2f(fmaxf(ov, 1e-12f));
        const float lqr = (1.0f - 0.5f*pc)*lb;

        const float qrmax = warpMaxF(lqr);
        const unsigned mr = __ballot_sync(FULLM, lqr == qrmax);

        if (lane == (j & 31)){
            keep1 = make_float2(q1max, __uint_as_float(m1));
            keepr = make_float2(qrmax, __uint_as_float(mr));
        }
        if ((j & 31) == 31){
            const size_t sidx = bbase + pbase + (j - 31) + lane;
            g_q1[sidx] = keep1;
            g_qr[sidx] = keepr;
        }
    }

    const float wc = warpSumF(accC);
    if (lane == 0) s_cacc[w] = wc;
    __syncthreads();
    if (tid == 0){
        double s = 0.0;
#pragma unroll
        for (int i = 0; i < 8; ++i) s += (double)s_cacc[i];
        g_basC[blockIdx.x] = s;
    }
}

// ---------------- kernel B: per-(b,o,type) 15th-largest threshold ----------------
__global__ void __launch_bounds__(256) kB(){
    const int gw   = (blockIdx.x*blockDim.x + threadIdx.x) >> 5;  // 0..2047
    const int lane = threadIdx.x & 31;
    const int b    = gw >> 6;
    const int rem  = gw & 63;
    const int type = rem >> 5;
    const int o    = rem & 31;

    const float2* __restrict__ dat = type ? g_qr : g_q1;
    const float floorv = type ? -CUDART_INF_F : 0.f;
    const size_t base = (size_t)b*PP;

    float list[NTOPK];
#pragma unroll
    for (int i = 0; i < NTOPK; ++i) list[i] = floorv;

    for (int i0 = lane; i0 < PP; i0 += 32*8){
        float2 v[8];
#pragma unroll
        for (int j = 0; j < 8; ++j) v[j] = __ldg(&dat[base + i0 + 32*j]);
#pragma unroll
        for (int j = 0; j < 8; ++j){
            const unsigned m = __float_as_uint(v[j].y);
            const float cand = ((m >> o) & 1u) ? v[j].x : floorv;
            if (cand > list[NTOPK-1]){
                list[NTOPK-1] = cand;
#pragma unroll
                for (int k = NTOPK-1; k > 0; --k){
                    if (list[k] > list[k-1]){ float t = list[k-1]; list[k-1] = list[k]; list[k] = t; }
                }
            }
        }
    }

    // warp merge-pop on floats (handles negatives / -inf)
    float thr = floorv;
#pragma unroll 1
    for (int r = 0; r < NTOPK; ++r){
        const float maxv = warpMaxF(list[0]);
        const unsigned who = __ballot_sync(FULLM, list[0] == maxv);
        thr = maxv;
        if (lane == (__ffs(who) - 1)){
#pragma unroll
            for (int j = 0; j < NTOPK-1; ++j) list[j] = list[j+1];
            list[NTOPK-1] = floorv;
        }
    }
    if (lane == 0) g_thr[type*BB*OO + b*OO + o] = thr;
}

// ---------------- kernel C: sparse corrections (thread per prior) ----------------
__global__ void __launch_bounds__(1024) kC(const float* __restrict__ loc,
                                           const float* __restrict__ conf,
                                           const float* __restrict__ priors,
                                           const float* __restrict__ targets){
    __shared__ float st[OO*5];
    __shared__ float sthr1[OO], sthrr[OO];
    __shared__ float s_l[32], s_c[32];
    __shared__ int   s_p[32], s_m[32];

    const int blocks_per_b = NCB2 / BB;       // 24
    const int b   = blockIdx.x / blocks_per_b;
    const int seg = blockIdx.x % blocks_per_b;
    const int tid = threadIdx.x;
    const int lane = tid & 31;
    const int w = tid >> 5;

    if (tid < OO*5) st[tid] = targets[b*OO*5 + tid];
    if (tid >= 256 && tid < 288) sthr1[tid-256] = g_thr[b*OO + (tid-256)];
    if (tid >= 288 && tid < 320) sthrr[tid-288] = g_thr[BB*OO + b*OO + (tid-288)];
    __syncthreads();

    const int p = seg*1024 + tid;
    const size_t idx = (size_t)b*PP + p;

    const float2 a = g_q1[idx];
    const float2 r = g_qr[idx];
    const float v1 = a.x; unsigned m1 = __float_as_uint(a.y);
    const float vr = r.x; unsigned mr = __float_as_uint(r.y);

    int bo = -1;
    if (v1 > 0.f){
#pragma unroll 1
        while (m1){
            const int oo = __ffs(m1) - 1;
            if (v1 >= sthr1[oo]){ bo = oo; break; }
            m1 &= m1 - 1;
        }
    }
    int bor = -1;
    {
        // qr matrix is strictly positive in linear domain, so reference's q>0 is
        // vacuous; log-domain comparison vs threshold suffices.
#pragma unroll 1
        while (mr){
            const int oo = __ffs(mr) - 1;
            if (vr >= sthrr[oo]){ bor = oo; break; }
            mr &= mr - 1;
        }
    }

    float accC = 0.f, accL = 0.f;
    int cntM = 0, cntP = 0;

    if (bo >= 0){
        cntM = 1;
        const int tclass = (int)st[bo*5+4];
        const float l = __ldg(&conf[idx*CC + tclass]);
        const float t = v1;
        const float e = __expf(-fabsf(l));
        const float rr = __fdividef(1.f, 1.f + e);
        const float ps = (l >= 0.f) ? rr : (1.f - rr);
        const float sp = fmaxf(l, 0.f) + __logf(1.f + e);
        const float d = t - ps;
        accC = d*d*(sp - l*t) - ps*ps*sp;   // f(l,t) - f0(l)
    }
    if (bor >= 0){
        cntP = 1;
        const float4 pr = __ldg(&reinterpret_cast<const float4*>(priors)[p]);
        const float4 lc = __ldg(&reinterpret_cast<const float4*>(loc)[idx]);
        const float mx0 = st[bor*5+0], my0 = st[bor*5+1];
        const float mx1 = st[bor*5+2], my1 = st[bor*5+3];
        const float gx = ((mx0+mx1)*0.5f - pr.x) / (0.1f*pr.z);
        const float gy = ((my0+my1)*0.5f - pr.y) / (0.1f*pr.w);
        const float gw = logf(fmaxf((mx1-mx0)/pr.z, 1e-8f)) * 5.0f;
        const float gh = logf(fmaxf((my1-my0)/pr.w, 1e-8f)) * 5.0f;
        accL  = balanced_l1(fabsf(lc.x - gx));
        accL += balanced_l1(fabsf(lc.y - gy));
        accL += balanced_l1(fabsf(lc.z - gw));
        accL += balanced_l1(fabsf(lc.w - gh));
    }

    const float wl_ = warpSumF(accL);
    const float wc  = warpSumF(accC);
    int ip = cntP, im = cntM;
#pragma unroll
    for (int off = 16; off; off >>= 1){
        ip += __shfl_xor_sync(FULLM, ip, off);
        im += __shfl_xor_sync(FULLM, im, off);
    }
    if (lane == 0){ s_l[w] = wl_; s_c[w] = wc; s_p[w] = ip; s_m[w] = im; }
    __syncthreads();
    if (tid == 0){
        double dl = 0, dc = 0; int pp2 = 0, mm = 0;
#pragma unroll
        for (int i = 0; i < 32; ++i){ dl += (double)s_l[i]; dc += (double)s_c[i]; pp2 += s_p[i]; mm += s_m[i]; }
        double* g = g_pc + (size_t)blockIdx.x*4;
        g[0] = dl; g[1] = (double)pp2; g[2] = dc; g[3] = (double)mm;
    }
}

// ---------------- final deterministic reduction ----------------
__global__ void __launch_bounds__(512) kFinal(float* __restrict__ out){
    __shared__ double sh[16][4];
    __shared__ double shb[16];
    // each thread's metric slot is fixed: k = tid & 3 (since 512 % 4 == 0)
    double s = 0.0;
    for (int i = threadIdx.x; i < NCB2*4; i += 512) s += g_pc[i];
    double sb = 0.0;
    for (int i = threadIdx.x; i < NBLK; i += 512) sb += g_basC[i];

    const int lane = threadIdx.x & 31, w = threadIdx.x >> 5;
    // reduce within warp over lanes sharing the same k (offsets 4,8,16)
#pragma unroll
    for (int off = 16; off >= 4; off >>= 1) s += __shfl_xor_sync(FULLM, s, off);
    // full butterfly for base sum
#pragma unroll
    for (int off = 16; off; off >>= 1) sb += __shfl_xor_sync(FULLM, sb, off);
    if (lane < 4) sh[w][lane] = s;
    if (lane == 0) shb[w] = sb;
    __syncthreads();
    if (threadIdx.x == 0){
        double t[4] = {0,0,0,0};
        double tb = 0.0;
#pragma unroll
        for (int i = 0; i < 16; ++i){
#pragma unroll
            for (int k = 0; k < 4; ++k) t[k] += sh[i][k];
            tb += shb[i];
        }
        const double num_l = t[0], cnt_p = t[1], num_c = t[2] + tb, cnt_m = t[3];
        out[0] = (float)(num_l / fmax(cnt_p, 1.0));
        out[1] = (float)(num_c / fmax(cnt_m, 1.0));
    }
}

// ---------------- launch ----------------
extern "C" void kernel_launch(void* const* d_in, const int* in_sizes, int n_in,
                              void* d_out, int out_size){
    const float* loc     = (const float*)d_in[0];
    const float* conf    = (const float*)d_in[1];
    const float* priors  = (const float*)d_in[2];
    const float* targets = (const float*)d_in[3];
    float* out = (float*)d_out;

    kA<<<NBLK, 256>>>(loc, conf, priors, targets);
    kB<<<(2*BB*OO*32)/256, 256>>>();
    kC<<<NCB2, 1024>>>(loc, conf, priors, targets);
    kFinal<<<1, 512>>>(out);
}